// round 14
// baseline (speedup 1.0000x reference)
#include <cuda_runtime.h>
#include <cuda_bf16.h>
#include <cuda_fp16.h>
#include <math.h>
#include <stdint.h>

#define TOK   8192      // batch*seq tokens
#define DM    1024      // model dim
#define NFLAT 32768     // TOK * 4 groups
#define ED    256       // embedding dim
#define KC    8192      // codebook size
#define OUTN  (TOK*DM)  // 8388608

// ---------------- scratch (device globals: no runtime allocation) ----------
__device__ float    g_bufA[TOK*DM];
__device__ float    g_bufB[TOK*DM];
__device__ float    g_z[TOK*DM];
__device__ float    g_znorm[NFLAT];
__device__ float    g_cnorm[KC];
__device__ int      g_idx[NFLAT];
__device__ int      g_hist[KC];
__device__ double   g_part[4096];
__device__ unsigned g_cb8[KC*64];             // codebook e4m3 x 2^21 (2MB)
__device__ __half   g_wt[4][2*1024*1024];     // 4 weights x 2 fp16 planes [n][k] (16MB)
__device__ __half   g_asp[2*TOK*DM];          // activation fp16 planes (32MB)

#define LO_SCALE   2048.0f
#define LO_INV     (1.0f/2048.0f)
#define Q_SCALE    128.0f
#define Q_INV      (1.0f/128.0f)
#define Z8SCALE    16.0f
#define C8SCALE    2097152.0f                 // 2^21
#define D8SCALE    (-1.0f/16777216.0f)        // -2 / 2^25
#define VQ_MARGIN8 1.2e-3f

__device__ __forceinline__ float rsqrt_approx(float x)
{
    float y;
    asm("rsqrt.approx.f32 %0, %1;" : "=f"(y) : "f"(x));
    return y;
}
__device__ __forceinline__ uint32_t smem_u32(const void* p)
{
    uint32_t a;
    asm("{ .reg .u64 t; cvta.to.shared.u64 t, %1; cvt.u32.u64 %0, t; }"
        : "=r"(a) : "l"(p));
    return a;
}
__device__ __forceinline__ unsigned short f2e4m3x2(float lo, float hi)
{
    unsigned short r;
    asm("cvt.rn.satfinite.e4m3x2.f32 %0, %1, %2;" : "=h"(r) : "f"(hi), "f"(lo));
    return r;
}
// ---- baseline tensor-core + async-copy ops (compile at compute_103) ----
__device__ __forceinline__ void ldsm_x4(unsigned* r, uint32_t addr)
{
    asm volatile("ldmatrix.sync.aligned.m8n8.x4.shared.b16 {%0,%1,%2,%3}, [%4];"
                 : "=r"(r[0]), "=r"(r[1]), "=r"(r[2]), "=r"(r[3]) : "r"(addr));
}
__device__ __forceinline__ void mma_f16(float* d, const unsigned* a, const unsigned* b)
{
    asm volatile(
        "mma.sync.aligned.m16n8k16.row.col.f32.f16.f16.f32 "
        "{%0,%1,%2,%3}, {%4,%5,%6,%7}, {%8,%9}, {%0,%1,%2,%3};"
        : "+f"(d[0]), "+f"(d[1]), "+f"(d[2]), "+f"(d[3])
        : "r"(a[0]), "r"(a[1]), "r"(a[2]), "r"(a[3]), "r"(b[0]), "r"(b[1]));
}
__device__ __forceinline__ void mma_e4m3(float* d, const unsigned* a, const unsigned* b)
{
    asm volatile(
        "mma.sync.aligned.m16n8k32.row.col.f32.e4m3.e4m3.f32 "
        "{%0,%1,%2,%3}, {%4,%5,%6,%7}, {%8,%9}, {%0,%1,%2,%3};"
        : "+f"(d[0]), "+f"(d[1]), "+f"(d[2]), "+f"(d[3])
        : "r"(a[0]), "r"(a[1]), "r"(a[2]), "r"(a[3]), "r"(b[0]), "r"(b[1]));
}
__device__ __forceinline__ void cp16(uint32_t dst, const void* src)
{
    asm volatile("cp.async.cg.shared.global [%0], [%1], 16;" :: "r"(dst), "l"(src));
}
#define CP_COMMIT() asm volatile("cp.async.commit_group;" ::: "memory")
#define CP_WAIT1()  asm volatile("cp.async.wait_group 1;" ::: "memory")
#define CP_WAIT0()  asm volatile("cp.async.wait_group 0;" ::: "memory")

// -------- weight prep: transpose + fp16 split, all 4 weights in one -------
__global__ __launch_bounds__(256)
void wsplit_k(const float* __restrict__ W0, const float* __restrict__ W1,
              const float* __restrict__ W2, const float* __restrict__ W3)
{
    const float* W = (blockIdx.z == 0) ? W0 : (blockIdx.z == 1) ? W1
                   : (blockIdx.z == 2) ? W2 : W3;
    __half* Wt = &g_wt[blockIdx.z][0];
    __shared__ float t[32][33];
    const int k0 = blockIdx.y * 32, n0 = blockIdx.x * 32;
    const int tx = threadIdx.x & 31, ty = threadIdx.x >> 5;
#pragma unroll
    for (int r = 0; r < 4; r++)
        t[ty + r * 8][tx] = W[(size_t)(k0 + ty + r * 8) * 1024 + n0 + tx];
    __syncthreads();
#pragma unroll
    for (int r = 0; r < 4; r++) {
        int n = n0 + ty + r * 8, k = k0 + tx;
        float a = t[tx][ty + r * 8];
        __half h = __float2half_rn(a);
        float r1 = __fsub_rn(a, __half2float(h));
        __half l = __float2half_rn(r1 * LO_SCALE);
        size_t o = (size_t)n * 1024 + k;
        Wt[o] = h;
        Wt[1048576 + o] = l;
    }
}

// ---------------- activation split: fp32 -> 2 fp16 planes (lo scaled) -----
__global__ __launch_bounds__(256)
void asplit_k(const float* __restrict__ A)
{
    size_t i = (size_t)blockIdx.x * 256 + threadIdx.x;
    float2 v = reinterpret_cast<const float2*>(A)[i];
    __half2 h2 = __float22half2_rn(v);
    float2 hf = __half22float2(h2);
    float2 r1 = make_float2((v.x - hf.x) * LO_SCALE, (v.y - hf.y) * LO_SCALE);
    __half2 l2 = __float22half2_rn(r1);
    unsigned* p0 = reinterpret_cast<unsigned*>(g_asp);
    p0[i]           = *reinterpret_cast<unsigned*>(&h2);
    p0[4194304 + i] = *reinterpret_cast<unsigned*>(&l2);
}

// ---------------- codebook prep: norms (fp64) + e4m3 pack, one pass -------
__global__ __launch_bounds__(256)
void cbprep_k(const float* __restrict__ CB)
{
    int warp = (blockIdx.x * 256 + threadIdx.x) >> 5;
    int lane = threadIdx.x & 31;
    const float4* c4 = reinterpret_cast<const float4*>(CB + (size_t)warp * ED);
    float4 a = c4[lane * 2], b = c4[lane * 2 + 1];
    double s = (double)a.x * a.x + (double)a.y * a.y + (double)a.z * a.z + (double)a.w * a.w
             + (double)b.x * b.x + (double)b.y * b.y + (double)b.z * b.z + (double)b.w * b.w;
    for (int o = 16; o > 0; o >>= 1) s += __shfl_xor_sync(0xffffffffu, s, o);
    if (lane == 0) g_cnorm[warp] = (float)s;
    unsigned short l0 = f2e4m3x2(a.x * C8SCALE, a.y * C8SCALE);
    unsigned short h0 = f2e4m3x2(a.z * C8SCALE, a.w * C8SCALE);
    unsigned short l1 = f2e4m3x2(b.x * C8SCALE, b.y * C8SCALE);
    unsigned short h1 = f2e4m3x2(b.z * C8SCALE, b.w * C8SCALE);
    g_cb8[(size_t)warp * 64 + lane * 2]     = (unsigned)l0 | ((unsigned)h0 << 16);
    g_cb8[(size_t)warp * 64 + lane * 2 + 1] = (unsigned)l1 | ((unsigned)h1 << 16);
}

// ------- fp16 split-2 HMMA GEMM (encoder): tile 128x128, 512 thr, 1 CTA/SM
#define GBUF 40960
#define GEMM_PREFETCH(kt, buf)                                                        \
    do {                                                                              \
        uint32_t dstb = base + (buf) * GBUF;                                          \
        int r = tid >> 2, q = tid & 3;                                                \
        _Pragma("unroll")                                                             \
        for (int p = 0; p < 2; p++) {                                                 \
            cp16(dstb + p * 10240 + r * 80 + q * 16,                                  \
                 reinterpret_cast<const char*>(Ap + (size_t)p * 8388608 +             \
                     (size_t)(row0 + r) * 1024 + (kt) * 32) + q * 16);                \
            cp16(dstb + 20480 + p * 10240 + r * 80 + q * 16,                          \
                 reinterpret_cast<const char*>(Wt + (size_t)p * 1048576 +             \
                     (size_t)(col0 + r) * 1024 + (kt) * 32) + q * 16);                \
        }                                                                             \
    } while (0)

__global__ __launch_bounds__(512, 1)
void gemm_mma_k(const __half* __restrict__ Ap, const __half* __restrict__ Wt,
                const float* __restrict__ bias, float* __restrict__ C)
{
    extern __shared__ char sm[];
    const int tid = threadIdx.x, lane = tid & 31, wid = tid >> 5;
    const uint32_t base = smem_u32(sm);
    const int warp_m = (wid & 3) * 32, warp_n = (wid >> 2) * 32;
    const uint32_t aOff = (uint32_t)(warp_m + (lane & 15)) * 80 + ((lane & 16) ? 16 : 0);
    const uint32_t bOff = 20480u
                        + (uint32_t)(warp_n + (lane & 7) + ((lane & 16) ? 8 : 0)) * 80
                        + ((lane & 8) ? 16 : 0);

    for (int t = blockIdx.x; t < 512; t += gridDim.x) {
        const int row0 = (t >> 3) * 128, col0 = (t & 7) * 128;

        float acc0[2][4][4], acc1[2][4][4];
#pragma unroll
        for (int mt = 0; mt < 2; mt++)
#pragma unroll
            for (int nf = 0; nf < 4; nf++)
#pragma unroll
                for (int e = 0; e < 4; e++) { acc0[mt][nf][e] = 0.f; acc1[mt][nf][e] = 0.f; }

        GEMM_PREFETCH(0, 0);
        CP_COMMIT();

        for (int kt = 0; kt < 32; kt++) {
            if (kt + 1 < 32) {
                GEMM_PREFETCH(kt + 1, (kt + 1) & 1);
                CP_COMMIT();
                CP_WAIT1();
            } else {
                CP_WAIT0();
            }
            __syncthreads();
            const uint32_t bufb = base + (kt & 1) * GBUF;
            const uint32_t aAddr = bufb + aOff;
            const uint32_t bAddr = bufb + bOff;
#pragma unroll
            for (int ks = 0; ks < 2; ks++) {
                unsigned ah[2][4], al[2][4];
#pragma unroll
                for (int mt = 0; mt < 2; mt++) {
                    ldsm_x4(ah[mt], aAddr + mt * 1280 + ks * 32);
                    ldsm_x4(al[mt], aAddr + 10240 + mt * 1280 + ks * 32);
                }
#pragma unroll
                for (int tp = 0; tp < 2; tp++) {
                    unsigned bh[4], bl[4];
                    ldsm_x4(bh, bAddr + tp * 1280 + ks * 32);
                    ldsm_x4(bl, bAddr + 10240 + tp * 1280 + ks * 32);
#pragma unroll
                    for (int mt = 0; mt < 2; mt++) {
                        mma_f16(acc0[mt][2 * tp],     ah[mt], bh);
                        mma_f16(acc0[mt][2 * tp + 1], ah[mt], bh + 2);
                        mma_f16(acc1[mt][2 * tp],     ah[mt], bl);
                        mma_f16(acc1[mt][2 * tp + 1], ah[mt], bl + 2);
                        mma_f16(acc1[mt][2 * tp],     al[mt], bh);
                        mma_f16(acc1[mt][2 * tp + 1], al[mt], bh + 2);
                    }
                }
            }
            __syncthreads();
        }

#pragma unroll
        for (int mt = 0; mt < 2; mt++) {
            int gr = row0 + warp_m + mt * 16 + (lane >> 2);
#pragma unroll
            for (int nf = 0; nf < 4; nf++) {
                int gc = col0 + warp_n + nf * 8 + (lane & 3) * 2;
                float b0 = bias[gc], b1 = bias[gc + 1];
                float s0 = fmaf(acc1[mt][nf][0], LO_INV, acc0[mt][nf][0]);
                float s1 = fmaf(acc1[mt][nf][1], LO_INV, acc0[mt][nf][1]);
                float s2 = fmaf(acc1[mt][nf][2], LO_INV, acc0[mt][nf][2]);
                float s3 = fmaf(acc1[mt][nf][3], LO_INV, acc0[mt][nf][3]);
                float2 v0, v1;
                v0.x = fmaxf(__fadd_rn(s0, b0), 0.f);
                v0.y = fmaxf(__fadd_rn(s1, b1), 0.f);
                v1.x = fmaxf(__fadd_rn(s2, b0), 0.f);
                v1.y = fmaxf(__fadd_rn(s3, b1), 0.f);
                *reinterpret_cast<float2*>(&C[(size_t)gr * 1024 + gc]) = v0;
                *reinterpret_cast<float2*>(&C[(size_t)(gr + 8) * 1024 + gc]) = v1;
            }
        }
    }
}

// ------- fp16 single-plane HMMA GEMM (decoder): tile 256x128, 512 thr -----
#define G1BUF 30720
#define GEMM1_PREFETCH(kt, buf)                                                       \
    do {                                                                              \
        uint32_t dstb = base + (buf) * G1BUF;                                         \
        _Pragma("unroll")                                                             \
        for (int l = 0; l < 2; l++) {                                                 \
            int idx = tid + l * 512;                                                  \
            int r = idx >> 2, q = idx & 3;                                            \
            cp16(dstb + r * 80 + q * 16,                                              \
                 reinterpret_cast<const char*>(Ap +                                   \
                     (size_t)(row0 + r) * 1024 + (kt) * 32) + q * 16);                \
        }                                                                             \
        {                                                                             \
            int r = tid >> 2, q = tid & 3;                                            \
            cp16(dstb + 20480 + r * 80 + q * 16,                                      \
                 reinterpret_cast<const char*>(Wt +                                   \
                     (size_t)(col0 + r) * 1024 + (kt) * 32) + q * 16);                \
        }                                                                             \
    } while (0)

__global__ __launch_bounds__(512, 1)
void gemm1_mma_k(const __half* __restrict__ Ap, const __half* __restrict__ Wt,
                 const float* __restrict__ bias, float osc, float* __restrict__ C)
{
    extern __shared__ char sm[];
    const int tid = threadIdx.x, lane = tid & 31, wid = tid >> 5;
    const uint32_t base = smem_u32(sm);
    const int warp_m = (wid & 3) * 64, warp_n = (wid >> 2) * 32;
    const uint32_t aOff = (uint32_t)(warp_m + (lane & 15)) * 80 + ((lane & 16) ? 16 : 0);
    const uint32_t bOff = 20480u
                        + (uint32_t)(warp_n + (lane & 7) + ((lane & 16) ? 8 : 0)) * 80
                        + ((lane & 8) ? 16 : 0);

    for (int t = blockIdx.x; t < 256; t += gridDim.x) {
        const int row0 = (t >> 3) * 256, col0 = (t & 7) * 128;

        float acc[4][4][4];
#pragma unroll
        for (int mt = 0; mt < 4; mt++)
#pragma unroll
            for (int nf = 0; nf < 4; nf++)
#pragma unroll
                for (int e = 0; e < 4; e++) acc[mt][nf][e] = 0.f;

        GEMM1_PREFETCH(0, 0);
        CP_COMMIT();

        for (int kt = 0; kt < 32; kt++) {
            if (kt + 1 < 32) {
                GEMM1_PREFETCH(kt + 1, (kt + 1) & 1);
                CP_COMMIT();
                CP_WAIT1();
            } else {
                CP_WAIT0();
            }
            __syncthreads();
            const uint32_t bufb = base + (kt & 1) * G1BUF;
            const uint32_t aAddr = bufb + aOff;
            const uint32_t bAddr = bufb + bOff;
#pragma unroll
            for (int ks = 0; ks < 2; ks++) {
                unsigned ah[4][4];
#pragma unroll
                for (int mt = 0; mt < 4; mt++)
                    ldsm_x4(ah[mt], aAddr + mt * 1280 + ks * 32);
#pragma unroll
                for (int tp = 0; tp < 2; tp++) {
                    unsigned bh[4];
                    ldsm_x4(bh, bAddr + tp * 1280 + ks * 32);
#pragma unroll
                    for (int mt = 0; mt < 4; mt++) {
                        mma_f16(acc[mt][2 * tp],     ah[mt], bh);
                        mma_f16(acc[mt][2 * tp + 1], ah[mt], bh + 2);
                    }
                }
            }
            __syncthreads();
        }

#pragma unroll
        for (int mt = 0; mt < 4; mt++) {
            int gr = row0 + warp_m + mt * 16 + (lane >> 2);
#pragma unroll
            for (int nf = 0; nf < 4; nf++) {
                int gc = col0 + warp_n + nf * 8 + (lane & 3) * 2;
                float b0 = bias[gc], b1 = bias[gc + 1];
                float2 v0, v1;
                v0.x = fmaxf(fmaf(acc[mt][nf][0], osc, b0), 0.f);
                v0.y = fmaxf(fmaf(acc[mt][nf][1], osc, b1), 0.f);
                v1.x = fmaxf(fmaf(acc[mt][nf][2], osc, b0), 0.f);
                v1.y = fmaxf(fmaf(acc[mt][nf][3], osc, b1), 0.f);
                *reinterpret_cast<float2*>(&C[(size_t)gr * 1024 + gc]) = v0;
                *reinterpret_cast<float2*>(&C[(size_t)(gr + 8) * 1024 + gc]) = v1;
            }
        }
    }
}

// ---- LayerNorm (shuffle reduce); SPLIT: 0 none, 1 hi, 2 both; ZN: znorm --
template<int SPLIT, bool ZN>
__global__ __launch_bounds__(256)
void layernorm_k(const float* __restrict__ X, const float* __restrict__ g,
                 const float* __restrict__ b, float* __restrict__ Y)
{
    __shared__ float wpart[8];
    __shared__ double zpart[8];
    const int row = blockIdx.x;
    const int tid = threadIdx.x;
    const int lane = tid & 31, wid = tid >> 5;
    const float* x = X + (size_t)row * DM;
    float4 v = *reinterpret_cast<const float4*>(&x[tid * 4]);

    float s = v.x + v.y + v.z + v.w;
#pragma unroll
    for (int o = 16; o > 0; o >>= 1) s += __shfl_xor_sync(0xffffffffu, s, o);
    if (lane == 0) wpart[wid] = s;
    __syncthreads();
    float m = (wpart[0] + wpart[1] + wpart[2] + wpart[3]
             + wpart[4] + wpart[5] + wpart[6] + wpart[7]) * (1.f / 1024.f);
    __syncthreads();

    float dx = __fsub_rn(v.x, m), dy = __fsub_rn(v.y, m);
    float dz = __fsub_rn(v.z, m), dw = __fsub_rn(v.w, m);
    float s2 = dx * dx + dy * dy + dz * dz + dw * dw;
#pragma unroll
    for (int o = 16; o > 0; o >>= 1) s2 += __shfl_xor_sync(0xffffffffu, s2, o);
    if (lane == 0) wpart[wid] = s2;
    __syncthreads();
    float var = (wpart[0] + wpart[1] + wpart[2] + wpart[3]
               + wpart[4] + wpart[5] + wpart[6] + wpart[7]) * (1.f / 1024.f);
    float sc = rsqrt_approx(__fadd_rn(var, 1e-5f));

    float4 gg = *reinterpret_cast<const float4*>(&g[tid * 4]);
    float4 bb = *reinterpret_cast<const float4*>(&b[tid * 4]);
    float4 o4;
    o4.x = __fadd_rn(__fmul_rn(__fmul_rn(dx, sc), gg.x), bb.x);
    o4.y = __fadd_rn(__fmul_rn(__fmul_rn(dy, sc), gg.y), bb.y);
    o4.z = __fadd_rn(__fmul_rn(__fmul_rn(dz, sc), gg.z), bb.z);
    o4.w = __fadd_rn(__fmul_rn(__fmul_rn(dw, sc), gg.w), bb.w);
    *reinterpret_cast<float4*>(&Y[(size_t)row * DM + tid * 4]) = o4;

    if (SPLIT >= 1) {
        unsigned* au = reinterpret_cast<unsigned*>(g_asp);
        size_t bu = (size_t)row * 512 + tid * 2;
        __half2 h0 = __floats2half2_rn(o4.x, o4.y);
        __half2 h1 = __floats2half2_rn(o4.z, o4.w);
        au[bu]     = *reinterpret_cast<unsigned*>(&h0);
        au[bu + 1] = *reinterpret_cast<unsigned*>(&h1);
        if (SPLIT == 2) {
            float2 f0 = __half22float2(h0), f1 = __half22float2(h1);
            __half2 l0 = __floats2half2_rn((o4.x - f0.x) * LO_SCALE, (o4.y - f0.y) * LO_SCALE);
            __half2 l1 = __floats2half2_rn((o4.z - f1.x) * LO_SCALE, (o4.w - f1.y) * LO_SCALE);
            au[4194304 + bu]     = *reinterpret_cast<unsigned*>(&l0);
            au[4194304 + bu + 1] = *reinterpret_cast<unsigned*>(&l1);
        }
    }
    if (ZN) {
        double zs = (double)o4.x * o4.x + (double)o4.y * o4.y
                  + (double)o4.z * o4.z + (double)o4.w * o4.w;
#pragma unroll
        for (int o = 16; o > 0; o >>= 1) zs += __shfl_xor_sync(0xffffffffu, zs, o);
        if (lane == 0) zpart[wid] = zs;
        __syncthreads();
        if (tid < 4)
            g_znorm[row * 4 + tid] = (float)(zpart[2 * tid] + zpart[2 * tid + 1]);
    }
}

// ---------------- VQ: fp8 mma.sync sweep + exact fp32 refinement ----------
#define STR8 272
#define VQ8_BUF (64*STR8)
#define VQ8_SMEM (2*VQ8_BUF)

__device__ __forceinline__ void insert4(float* L, int* C, float d, int code)
{
    if (d < L[3]) {
        float dd = d; int cc = code;
#pragma unroll
        for (int s = 0; s < 4; s++) {
            if (dd < L[s]) {
                float tf = L[s]; int ti = C[s];
                L[s] = dd; C[s] = cc; dd = tf; cc = ti;
            }
        }
    }
}

#define VQ8_PREFETCH(n0, buf)                                                 \
    do {                                                                      \
        const char* srcc = reinterpret_cast<const char*>(g_cb8) + (size_t)(n0) * 256; \
        uint32_t dstb = smBase + (buf) * VQ8_BUF;                             \
        _Pragma("unroll")                                                     \
        for (int j = 0; j < 4; j++) {                                         \
            int idx = tid + j * 256;                                          \
            int code = idx >> 4, q = idx & 15;                                \
            cp16(dstb + code * STR8 + q * 16, srcc + (size_t)idx * 16);       \
        }                                                                     \
    } while (0)

__global__ __launch_bounds__(256, 2)
void vq_mma_k(const float* __restrict__ Z, const float* __restrict__ CB,
              int* __restrict__ out_idx)
{
    extern __shared__ char sm[];
    const int tid  = threadIdx.x;
    const int lane = tid & 31;
    const int wid  = tid >> 5;
    const int row0 = blockIdx.x * 128;
    const uint32_t smBase = smem_u32(sm);

#pragma unroll
    for (int j = 0; j < 32; j++) {
        int idx = tid + j * 256;
        int m = idx >> 6, b4 = (idx & 63) * 4;
        float4 v = *reinterpret_cast<const float4*>(Z + (size_t)(row0 + m) * ED + b4);
        unsigned short l = f2e4m3x2(v.x * Z8SCALE, v.y * Z8SCALE);
        unsigned short h = f2e4m3x2(v.z * Z8SCALE, v.w * Z8SCALE);
        *reinterpret_cast<unsigned*>(sm + m * STR8 + b4) = (unsigned)l | ((unsigned)h << 16);
    }
    __syncthreads();

    unsigned a[8][4];
    {
        int rowA = wid * 16 + (lane & 15);
        int kofs = (lane & 16) ? 16 : 0;
        uint32_t base = smBase + rowA * STR8 + kofs;
#pragma unroll
        for (int ks = 0; ks < 8; ks++)
            ldsm_x4(a[ks], base + ks * 32);
    }
    __syncthreads();

    float L0[4], L1[4]; int C0[4], C1[4];
#pragma unroll
    for (int e = 0; e < 4; e++) { L0[e] = L1[e] = 3.4e38f; C0[e] = C1[e] = 0x7fffffff; }

    const uint32_t bOff = (uint32_t)((lane & 7) + ((lane & 16) ? 8 : 0)) * STR8
                        + ((lane & 8) ? 16 : 0);
    const int r  = lane >> 2;
    const int c2 = (lane & 3) * 2;

    VQ8_PREFETCH(0, 0);
    CP_COMMIT();

    for (int ci = 0; ci < 128; ci++) {
        const int n0 = ci * 64;
        if (ci + 1 < 128) {
            VQ8_PREFETCH(n0 + 64, (ci + 1) & 1);
            CP_COMMIT();
            CP_WAIT1();
        } else {
            CP_WAIT0();
        }
        __syncthreads();

        const uint32_t bB = smBase + (ci & 1) * VQ8_BUF + bOff;

        float acc[8][4];
#pragma unroll
        for (int t = 0; t < 8; t++) { acc[t][0] = acc[t][1] = acc[t][2] = acc[t][3] = 0.f; }

#pragma unroll
        for (int ks = 0; ks < 8; ks++) {
#pragma unroll
            for (int tp = 0; tp < 4; tp++) {
                unsigned bb[4];
                ldsm_x4(bb, bB + tp * 16 * STR8 + ks * 32);
                mma_e4m3(acc[2 * tp],     a[ks], bb);
                mma_e4m3(acc[2 * tp + 1], a[ks], bb + 2);
            }
        }

        const float2* cn2 = reinterpret_cast<const float2*>(g_cnorm + n0);
#pragma unroll
        for (int t = 0; t < 8; t++) {
            int cb = t * 8 + c2;
            float2 c01 = cn2[cb >> 1];
            insert4(L0, C0, fmaf(acc[t][0], D8SCALE, c01.x), n0 + cb);
            insert4(L0, C0, fmaf(acc[t][1], D8SCALE, c01.y), n0 + cb + 1);
            insert4(L1, C1, fmaf(acc[t][2], D8SCALE, c01.x), n0 + cb);
            insert4(L1, C1, fmaf(acc[t][3], D8SCALE, c01.y), n0 + cb + 1);
        }
        __syncthreads();
    }

    float* dS = reinterpret_cast<float*>(sm);
    int*   cS = reinterpret_cast<int*>(sm + 8192);
    {
        int base0 = (wid * 16 + r)     * 16 + (lane & 3) * 4;
        int base1 = (wid * 16 + r + 8) * 16 + (lane & 3) * 4;
#pragma unroll
        for (int e = 0; e < 4; e++) {
            dS[base0 + e] = L0[e]; cS[base0 + e] = C0[e];
            dS[base1 + e] = L1[e]; cS[base1 + e] = C1[e];
        }
    }
    __syncthreads();

    if (tid < 128) {
        const int row = row0 + tid;
        const float* dr = dS + tid * 16;
        const int*   cr = cS + tid * 16;
        float amin = dr[0];
#pragma unroll
        for (int e = 1; e < 16; e++) amin = fminf(amin, dr[e]);
        const float thr = amin + VQ_MARGIN8;
        const float zn = g_znorm[row];
        const float4* z4 = reinterpret_cast<const float4*>(Z + (size_t)row * ED);
        float best = 3.4e38f; int bi = 0x7fffffff;
        for (int e = 0; e < 16; e++) {
            if (dr[e] <= thr) {
                int code = cr[e];
                const float4* c4 = reinterpret_cast<const float4*>(CB + (size_t)code * ED);
                float accv = 0.f;
#pragma unroll 8
                for (int i = 0; i < 64; i++) {
                    float4 zv = z4[i], cv = c4[i];
                    accv = fmaf(zv.x, cv.x, accv);
                    accv = fmaf(zv.y, cv.y, accv);
                    accv = fmaf(zv.z, cv.z, accv);
                    accv = fmaf(zv.w, cv.w, accv);
                }
                float dex = __fsub_rn(__fadd_rn(zn, g_cnorm[code]), __fmul_rn(2.f, accv));
                if (dex < best || (dex == best && code < bi)) { best = dex; bi = code; }
            }
        }
        out_idx[row] = bi;
    }
}

// ---------------- histogram zero ------------------------------------------
__global__ __launch_bounds__(256)
void zero_hist_k()
{
    int i = blockIdx.x * 256 + threadIdx.x;
    if (i < KC) g_hist[i] = 0;
}

// ---- gather: ST rounding -> fp16 hi plane (x128) + hist + loss partial ---
__global__ __launch_bounds__(256)
void gather_hist_k(const float* __restrict__ CB)
{
    __shared__ double red[256];
    int warp = (blockIdx.x * 256 + threadIdx.x) >> 5;
    int lane = threadIdx.x & 31;
    int n = g_idx[warp];
    const float4* src = reinterpret_cast<const float4*>(CB + (size_t)n * ED);
    const float4* zsrc = reinterpret_cast<const float4*>(g_z + (size_t)warp * ED);
    unsigned* au = reinterpret_cast<unsigned*>(g_asp);
    double ls = 0.0;
#pragma unroll
    for (int h = 0; h < 2; h++) {
        float4 q = src[lane + h * 32];
        float4 z = zsrc[lane + h * 32];
        float dxx = __fsub_rn(q.x, z.x), dyy = __fsub_rn(q.y, z.y);
        float dzz = __fsub_rn(q.z, z.z), dww = __fsub_rn(q.w, z.w);
        float4 o;
        o.x = __fadd_rn(z.x, dxx);
        o.y = __fadd_rn(z.y, dyy);
        o.z = __fadd_rn(z.z, dzz);
        o.w = __fadd_rn(z.w, dww);
        float ex = __fsub_rn(o.x, z.x), ey = __fsub_rn(o.y, z.y);
        float ez = __fsub_rn(o.z, z.z), ew = __fsub_rn(o.w, z.w);
        ls += (double)ex * ex + (double)ey * ey + (double)ez * ez + (double)ew * ew;
        __half2 h0 = __floats2half2_rn(o.x * Q_SCALE, o.y * Q_SCALE);
        __half2 h1 = __floats2half2_rn(o.z * Q_SCALE, o.w * Q_SCALE);
        size_t bu = (size_t)warp * 128 + (size_t)(lane + h * 32) * 2;
        au[bu]     = *reinterpret_cast<unsigned*>(&h0);
        au[bu + 1] = *reinterpret_cast<unsigned*>(&h1);
    }
    if (lane == 0) atomicAdd(&g_hist[n], 1);
    red[threadIdx.x] = ls;
    __syncthreads();
    for (int o = 128; o > 0; o >>= 1) {
        if (threadIdx.x < o) red[threadIdx.x] += red[threadIdx.x + o];
        __syncthreads();
    }
    if (threadIdx.x == 0) g_part[blockIdx.x] = red[0];
}

// ---------------- finalize loss + perplexity ------------------------------
__global__ __launch_bounds__(256)
void finalize_k(float* __restrict__ out)
{
    __shared__ double red[256];
    int t = threadIdx.x;
    double s = 0.0;
    for (int k = 0; k < 16; k++) s += g_part[t + k * 256];
    red[t] = s;
    __syncthreads();
    for (int o = 128; o > 0; o >>= 1) { if (t < o) red[t] += red[t + o]; __syncthreads(); }
    double total = red[0];
    __syncthreads();
    double ps = 0.0;
    for (int k = 0; k < 32; k++) {
        int idx = t + k * 256;
        float p = (float)g_hist[idx] / 32768.f;
        ps += (double)__fmul_rn(p, logf(__fadd_rn(p, 1e-10f)));
    }
    red[t] = ps;
    __syncthreads();
    for (int o = 128; o > 0; o >>= 1) { if (t < o) red[t] += red[t + o]; __syncthreads(); }
    if (t == 0) {
        float m = (float)(total / 8388608.0);
        out[OUTN]     = __fadd_rn(m, __fmul_rn(0.25f, m));
        out[OUTN + 1] = expf(-(float)red[0]);
    }
}

// ---------------- launch ---------------------------------------------------
extern "C" void kernel_launch(void* const* d_in, const int* in_sizes, int n_in,
                              void* d_out, int out_size)
{
    const float* x    = (const float*)d_in[0];
    const float* We1  = (const float*)d_in[1];
    const float* be1  = (const float*)d_in[2];
    const float* ge1  = (const float*)d_in[3];
    const float* bne1 = (const float*)d_in[4];
    const float* We2  = (const float*)d_in[5];
    const float* be2  = (const float*)d_in[6];
    const float* ge2  = (const float*)d_in[7];
    const float* bne2 = (const float*)d_in[8];
    const float* Wd1  = (const float*)d_in[9];
    const float* bd1  = (const float*)d_in[10];
    const float* gd1  = (const float*)d_in[11];
    const float* bnd1 = (const float*)d_in[12];
    const float* Wd2  = (const float*)d_in[13];
    const float* bd2  = (const float*)d_in[14];
    const float* gd2  = (const float*)d_in[15];
    const float* bnd2 = (const float*)d_in[16];
    const float* CB   = (const float*)d_in[17];
    float* out = (float*)d_out;

    float *bufA, *bufB, *zp;
    int *idxp;
    __half *wt, *asp;
    cudaGetSymbolAddress((void**)&bufA, g_bufA);
    cudaGetSymbolAddress((void**)&bufB, g_bufB);
    cudaGetSymbolAddress((void**)&zp,   g_z);
    cudaGetSymbolAddress((void**)&idxp, g_idx);
    cudaGetSymbolAddress((void**)&wt,   g_wt);
    cudaGetSymbolAddress((void**)&asp,  g_asp);

    int nsm = 148;
    cudaDeviceGetAttribute(&nsm, cudaDevAttrMultiProcessorCount, 0);

    cudaFuncSetAttribute(vq_mma_k, cudaFuncAttributeMaxDynamicSharedMemorySize, VQ8_SMEM);
    cudaFuncSetAttribute(gemm_mma_k, cudaFuncAttributeMaxDynamicSharedMemorySize, 2 * GBUF);
    cudaFuncSetAttribute(gemm1_mma_k, cudaFuncAttributeMaxDynamicSharedMemorySize, 2 * G1BUF);

    dim3 wg(32, 32, 4);

    // prep
    wsplit_k<<<wg, 256>>>(We1, We2, Wd1, Wd2);
    asplit_k<<<16384, 256>>>(x);
    cbprep_k<<<KC / 8, 256>>>(CB);
    zero_hist_k<<<KC / 256, 256>>>();

    // encoder (persistent split-2 fp16 GEMMs; LN1 emits planes, LN2 emits znorm)
    gemm_mma_k<<<nsm, 512, 2 * GBUF>>>(asp, wt, be1, bufA);
    layernorm_k<2, false><<<TOK, 256>>>(bufA, ge1, bne1, bufB);
    gemm_mma_k<<<nsm, 512, 2 * GBUF>>>(asp, wt + 1 * 2097152, be2, bufA);
    layernorm_k<0, true><<<TOK, 256>>>(bufA, ge2, bne2, zp);

    // vector quantization (fp8 sweep + exact refinement)
    vq_mma_k<<<NFLAT / 128, 256, VQ8_SMEM>>>(zp, CB, idxp);
    gather_hist_k<<<NFLAT / 8, 256>>>(CB);   // emits decoder planes + loss partials

    // decoder (persistent single-plane fp16 GEMMs)
    gemm1_mma_k<<<nsm, 512, 2 * G1BUF>>>(asp, wt + 2 * 2097152, bd1, Q_INV, bufA);
    layernorm_k<1, false><<<TOK, 256>>>(bufA, gd1, bnd1, bufB);
    gemm1_mma_k<<<nsm, 512, 2 * G1BUF>>>(asp, wt + 3 * 2097152, bd2, 1.0f, bufA);
    layernorm_k<0, false><<<TOK, 256>>>(bufA, gd2, bnd2, out);

    // scalars
    finalize_k<<<1, 256>>>(out);
}

// round 15
// speedup vs baseline: 1.0499x; 1.0499x over previous
#include <cuda_runtime.h>
#include <cuda_bf16.h>
#include <cuda_fp16.h>
#include <math.h>
#include <stdint.h>

#define TOK   8192      // batch*seq tokens
#define DM    1024      // model dim
#define NFLAT 32768     // TOK * 4 groups
#define ED    256       // embedding dim
#define KC    8192      // codebook size
#define OUTN  (TOK*DM)  // 8388608

// ---------------- scratch (device globals: no runtime allocation) ----------
__device__ float    g_bufA[TOK*DM];
__device__ float    g_bufB[TOK*DM];
__device__ float    g_z[TOK*DM];
__device__ float    g_znorm[NFLAT];
__device__ float    g_cnorm[KC];
__device__ int      g_idx[NFLAT];
__device__ int      g_hist[KC];
__device__ double   g_part[4096];
__device__ unsigned g_cb8[KC*64];             // codebook e4m3 x 2^21 (2MB)
__device__ __half   g_wt[4][2*1024*1024];     // 4 weights x 2 fp16 planes [n][k] (16MB)
__device__ __half   g_asp[2*TOK*DM];          // activation fp16 planes (32MB)

#define LO_SCALE   2048.0f
#define LO_INV     (1.0f/2048.0f)
#define Q_SCALE    128.0f
#define Q_INV      (1.0f/128.0f)
#define Z8SCALE    16.0f
#define C8SCALE    2097152.0f                 // 2^21
#define D8SCALE    (-1.0f/16777216.0f)        // -2 / 2^25
#define VQ_MARGIN8 1.2e-3f

__device__ __forceinline__ float rsqrt_approx(float x)
{
    float y;
    asm("rsqrt.approx.f32 %0, %1;" : "=f"(y) : "f"(x));
    return y;
}
__device__ __forceinline__ uint32_t smem_u32(const void* p)
{
    uint32_t a;
    asm("{ .reg .u64 t; cvta.to.shared.u64 t, %1; cvt.u32.u64 %0, t; }"
        : "=r"(a) : "l"(p));
    return a;
}
__device__ __forceinline__ unsigned short f2e4m3x2(float lo, float hi)
{
    unsigned short r;
    asm("cvt.rn.satfinite.e4m3x2.f32 %0, %1, %2;" : "=h"(r) : "f"(hi), "f"(lo));
    return r;
}
// ---- baseline tensor-core + async-copy ops (compile at compute_103) ----
__device__ __forceinline__ void ldsm_x4(unsigned* r, uint32_t addr)
{
    asm volatile("ldmatrix.sync.aligned.m8n8.x4.shared.b16 {%0,%1,%2,%3}, [%4];"
                 : "=r"(r[0]), "=r"(r[1]), "=r"(r[2]), "=r"(r[3]) : "r"(addr));
}
__device__ __forceinline__ void mma_f16(float* d, const unsigned* a, const unsigned* b)
{
    asm volatile(
        "mma.sync.aligned.m16n8k16.row.col.f32.f16.f16.f32 "
        "{%0,%1,%2,%3}, {%4,%5,%6,%7}, {%8,%9}, {%0,%1,%2,%3};"
        : "+f"(d[0]), "+f"(d[1]), "+f"(d[2]), "+f"(d[3])
        : "r"(a[0]), "r"(a[1]), "r"(a[2]), "r"(a[3]), "r"(b[0]), "r"(b[1]));
}
__device__ __forceinline__ void mma_e4m3(float* d, const unsigned* a, const unsigned* b)
{
    asm volatile(
        "mma.sync.aligned.m16n8k32.row.col.f32.e4m3.e4m3.f32 "
        "{%0,%1,%2,%3}, {%4,%5,%6,%7}, {%8,%9}, {%0,%1,%2,%3};"
        : "+f"(d[0]), "+f"(d[1]), "+f"(d[2]), "+f"(d[3])
        : "r"(a[0]), "r"(a[1]), "r"(a[2]), "r"(a[3]), "r"(b[0]), "r"(b[1]));
}
__device__ __forceinline__ void cp16(uint32_t dst, const void* src)
{
    asm volatile("cp.async.cg.shared.global [%0], [%1], 16;" :: "r"(dst), "l"(src));
}
#define CP_COMMIT() asm volatile("cp.async.commit_group;" ::: "memory")
#define CP_WAIT1()  asm volatile("cp.async.wait_group 1;" ::: "memory")
#define CP_WAIT0()  asm volatile("cp.async.wait_group 0;" ::: "memory")

// -------- weight prep: transpose + fp16 split, all 4 weights in one -------
__global__ __launch_bounds__(256)
void wsplit_k(const float* __restrict__ W0, const float* __restrict__ W1,
              const float* __restrict__ W2, const float* __restrict__ W3)
{
    const float* W = (blockIdx.z == 0) ? W0 : (blockIdx.z == 1) ? W1
                   : (blockIdx.z == 2) ? W2 : W3;
    __half* Wt = &g_wt[blockIdx.z][0];
    __shared__ float t[32][33];
    const int k0 = blockIdx.y * 32, n0 = blockIdx.x * 32;
    const int tx = threadIdx.x & 31, ty = threadIdx.x >> 5;
#pragma unroll
    for (int r = 0; r < 4; r++)
        t[ty + r * 8][tx] = W[(size_t)(k0 + ty + r * 8) * 1024 + n0 + tx];
    __syncthreads();
#pragma unroll
    for (int r = 0; r < 4; r++) {
        int n = n0 + ty + r * 8, k = k0 + tx;
        float a = t[tx][ty + r * 8];
        __half h = __float2half_rn(a);
        float r1 = __fsub_rn(a, __half2float(h));
        __half l = __float2half_rn(r1 * LO_SCALE);
        size_t o = (size_t)n * 1024 + k;
        Wt[o] = h;
        Wt[1048576 + o] = l;
    }
}

// ---------------- activation split: fp32 -> 2 fp16 planes (lo scaled) -----
__global__ __launch_bounds__(256)
void asplit_k(const float* __restrict__ A)
{
    size_t i = (size_t)blockIdx.x * 256 + threadIdx.x;
    float2 v = reinterpret_cast<const float2*>(A)[i];
    __half2 h2 = __float22half2_rn(v);
    float2 hf = __half22float2(h2);
    float2 r1 = make_float2((v.x - hf.x) * LO_SCALE, (v.y - hf.y) * LO_SCALE);
    __half2 l2 = __float22half2_rn(r1);
    unsigned* p0 = reinterpret_cast<unsigned*>(g_asp);
    p0[i]           = *reinterpret_cast<unsigned*>(&h2);
    p0[4194304 + i] = *reinterpret_cast<unsigned*>(&l2);
}

// ---------------- codebook prep: norms (fp64) + e4m3 pack, one pass -------
__global__ __launch_bounds__(256)
void cbprep_k(const float* __restrict__ CB)
{
    int warp = (blockIdx.x * 256 + threadIdx.x) >> 5;
    int lane = threadIdx.x & 31;
    const float4* c4 = reinterpret_cast<const float4*>(CB + (size_t)warp * ED);
    float4 a = c4[lane * 2], b = c4[lane * 2 + 1];
    double s = (double)a.x * a.x + (double)a.y * a.y + (double)a.z * a.z + (double)a.w * a.w
             + (double)b.x * b.x + (double)b.y * b.y + (double)b.z * b.z + (double)b.w * b.w;
    for (int o = 16; o > 0; o >>= 1) s += __shfl_xor_sync(0xffffffffu, s, o);
    if (lane == 0) g_cnorm[warp] = (float)s;
    unsigned short l0 = f2e4m3x2(a.x * C8SCALE, a.y * C8SCALE);
    unsigned short h0 = f2e4m3x2(a.z * C8SCALE, a.w * C8SCALE);
    unsigned short l1 = f2e4m3x2(b.x * C8SCALE, b.y * C8SCALE);
    unsigned short h1 = f2e4m3x2(b.z * C8SCALE, b.w * C8SCALE);
    g_cb8[(size_t)warp * 64 + lane * 2]     = (unsigned)l0 | ((unsigned)h0 << 16);
    g_cb8[(size_t)warp * 64 + lane * 2 + 1] = (unsigned)l1 | ((unsigned)h1 << 16);
}

// ------- fp16 split-2 HMMA GEMM (encoder): 128x64 tile, 3-stage pipeline --
#define GBUF 30720
#define GEMM_PREFETCH(kt, buf)                                                        \
    do {                                                                              \
        uint32_t dstb = base + (buf) * GBUF;                                          \
        _Pragma("unroll")                                                             \
        for (int l = 0; l < 2; l++) {                                                 \
            int idx = tid + l * 256;                                                  \
            int r = idx >> 2, q = idx & 3;                                            \
            _Pragma("unroll")                                                         \
            for (int p = 0; p < 2; p++)                                               \
                cp16(dstb + p * 10240 + r * 80 + q * 16,                              \
                     reinterpret_cast<const char*>(Ap + (size_t)p * 8388608 +         \
                         (size_t)(row0 + r) * 1024 + (kt) * 32) + q * 16);            \
        }                                                                             \
        {                                                                             \
            int r = tid >> 2, q = tid & 3;                                            \
            _Pragma("unroll")                                                         \
            for (int p = 0; p < 2; p++)                                               \
                cp16(dstb + 20480 + p * 5120 + r * 80 + q * 16,                       \
                     reinterpret_cast<const char*>(Wt + (size_t)p * 1048576 +         \
                         (size_t)(col0 + r) * 1024 + (kt) * 32) + q * 16);            \
        }                                                                             \
    } while (0)

__global__ __launch_bounds__(256, 2)
void gemm_mma_k(const __half* __restrict__ Ap, const __half* __restrict__ Wt,
                const float* __restrict__ bias, float* __restrict__ C)
{
    extern __shared__ char sm[];
    const int tid = threadIdx.x, lane = tid & 31, wid = tid >> 5;
    const uint32_t base = smem_u32(sm);
    const int warp_m = (wid & 3) * 32, warp_n = (wid >> 2) * 32;
    const uint32_t aOff = (uint32_t)(warp_m + (lane & 15)) * 80 + ((lane & 16) ? 16 : 0);
    const uint32_t bOff = 20480u
                        + (uint32_t)(warp_n + (lane & 7) + ((lane & 16) ? 8 : 0)) * 80
                        + ((lane & 8) ? 16 : 0);

    for (int t = blockIdx.x; t < 1024; t += gridDim.x) {
        const int row0 = (t >> 4) * 128, col0 = (t & 15) * 64;

        float acc0[2][4][4], acc1[2][4][4];
#pragma unroll
        for (int mt = 0; mt < 2; mt++)
#pragma unroll
            for (int nf = 0; nf < 4; nf++)
#pragma unroll
                for (int e = 0; e < 4; e++) { acc0[mt][nf][e] = 0.f; acc1[mt][nf][e] = 0.f; }

        GEMM_PREFETCH(0, 0);
        CP_COMMIT();
        GEMM_PREFETCH(1, 1);
        CP_COMMIT();

        int cur = 0, nxt = 2;
        for (int kt = 0; kt < 32; kt++) {
            if (kt < 31) CP_WAIT1(); else CP_WAIT0();
            __syncthreads();                     // buf 'cur' ready; prev reads done
            if (kt + 2 < 32) {
                GEMM_PREFETCH(kt + 2, nxt);
                CP_COMMIT();
            }
            const uint32_t bufb = base + cur * GBUF;
            const uint32_t aAddr = bufb + aOff;
            const uint32_t bAddr = bufb + bOff;
#pragma unroll
            for (int ks = 0; ks < 2; ks++) {
                unsigned ah[2][4], al[2][4];
#pragma unroll
                for (int mt = 0; mt < 2; mt++) {
                    ldsm_x4(ah[mt], aAddr + mt * 1280 + ks * 32);
                    ldsm_x4(al[mt], aAddr + 10240 + mt * 1280 + ks * 32);
                }
#pragma unroll
                for (int tp = 0; tp < 2; tp++) {
                    unsigned bh[4], bl[4];
                    ldsm_x4(bh, bAddr + tp * 1280 + ks * 32);
                    ldsm_x4(bl, bAddr + 5120 + tp * 1280 + ks * 32);
#pragma unroll
                    for (int mt = 0; mt < 2; mt++) {
                        mma_f16(acc0[mt][2 * tp],     ah[mt], bh);
                        mma_f16(acc0[mt][2 * tp + 1], ah[mt], bh + 2);
                        mma_f16(acc1[mt][2 * tp],     ah[mt], bl);
                        mma_f16(acc1[mt][2 * tp + 1], ah[mt], bl + 2);
                        mma_f16(acc1[mt][2 * tp],     al[mt], bh);
                        mma_f16(acc1[mt][2 * tp + 1], al[mt], bh + 2);
                    }
                }
            }
            cur = (cur == 2) ? 0 : cur + 1;
            nxt = (nxt == 2) ? 0 : nxt + 1;
        }
        __syncthreads();                         // tile done before next reuse

#pragma unroll
        for (int mt = 0; mt < 2; mt++) {
            int gr = row0 + warp_m + mt * 16 + (lane >> 2);
#pragma unroll
            for (int nf = 0; nf < 4; nf++) {
                int gc = col0 + warp_n + nf * 8 + (lane & 3) * 2;
                float b0 = bias[gc], b1 = bias[gc + 1];
                float s0 = fmaf(acc1[mt][nf][0], LO_INV, acc0[mt][nf][0]);
                float s1 = fmaf(acc1[mt][nf][1], LO_INV, acc0[mt][nf][1]);
                float s2 = fmaf(acc1[mt][nf][2], LO_INV, acc0[mt][nf][2]);
                float s3 = fmaf(acc1[mt][nf][3], LO_INV, acc0[mt][nf][3]);
                float2 v0, v1;
                v0.x = fmaxf(__fadd_rn(s0, b0), 0.f);
                v0.y = fmaxf(__fadd_rn(s1, b1), 0.f);
                v1.x = fmaxf(__fadd_rn(s2, b0), 0.f);
                v1.y = fmaxf(__fadd_rn(s3, b1), 0.f);
                *reinterpret_cast<float2*>(&C[(size_t)gr * 1024 + gc]) = v0;
                *reinterpret_cast<float2*>(&C[(size_t)(gr + 8) * 1024 + gc]) = v1;
            }
        }
    }
}

// ------- fp16 single-plane HMMA GEMM (decoder): 128x64, 3-stage -----------
#define G1BUF 15360
#define GEMM1_PREFETCH(kt, buf)                                                       \
    do {                                                                              \
        uint32_t dstb = base + (buf) * G1BUF;                                         \
        _Pragma("unroll")                                                             \
        for (int l = 0; l < 2; l++) {                                                 \
            int idx = tid + l * 256;                                                  \
            int r = idx >> 2, q = idx & 3;                                            \
            cp16(dstb + r * 80 + q * 16,                                              \
                 reinterpret_cast<const char*>(Ap +                                   \
                     (size_t)(row0 + r) * 1024 + (kt) * 32) + q * 16);                \
        }                                                                             \
        {                                                                             \
            int r = tid >> 2, q = tid & 3;                                            \
            cp16(dstb + 10240 + r * 80 + q * 16,                                      \
                 reinterpret_cast<const char*>(Wt +                                   \
                     (size_t)(col0 + r) * 1024 + (kt) * 32) + q * 16);                \
        }                                                                             \
    } while (0)

__global__ __launch_bounds__(256, 2)
void gemm1_mma_k(const __half* __restrict__ Ap, const __half* __restrict__ Wt,
                 const float* __restrict__ bias, float osc, float* __restrict__ C)
{
    extern __shared__ char sm[];
    const int tid = threadIdx.x, lane = tid & 31, wid = tid >> 5;
    const uint32_t base = smem_u32(sm);
    const int warp_m = (wid & 3) * 32, warp_n = (wid >> 2) * 32;
    const uint32_t aOff = (uint32_t)(warp_m + (lane & 15)) * 80 + ((lane & 16) ? 16 : 0);
    const uint32_t bOff = 10240u
                        + (uint32_t)(warp_n + (lane & 7) + ((lane & 16) ? 8 : 0)) * 80
                        + ((lane & 8) ? 16 : 0);

    for (int t = blockIdx.x; t < 1024; t += gridDim.x) {
        const int row0 = (t >> 4) * 128, col0 = (t & 15) * 64;

        float acc[2][4][4];
#pragma unroll
        for (int mt = 0; mt < 2; mt++)
#pragma unroll
            for (int nf = 0; nf < 4; nf++)
#pragma unroll
                for (int e = 0; e < 4; e++) acc[mt][nf][e] = 0.f;

        GEMM1_PREFETCH(0, 0);
        CP_COMMIT();
        GEMM1_PREFETCH(1, 1);
        CP_COMMIT();

        int cur = 0, nxt = 2;
        for (int kt = 0; kt < 32; kt++) {
            if (kt < 31) CP_WAIT1(); else CP_WAIT0();
            __syncthreads();
            if (kt + 2 < 32) {
                GEMM1_PREFETCH(kt + 2, nxt);
                CP_COMMIT();
            }
            const uint32_t bufb = base + cur * G1BUF;
            const uint32_t aAddr = bufb + aOff;
            const uint32_t bAddr = bufb + bOff;
#pragma unroll
            for (int ks = 0; ks < 2; ks++) {
                unsigned ah[2][4];
#pragma unroll
                for (int mt = 0; mt < 2; mt++)
                    ldsm_x4(ah[mt], aAddr + mt * 1280 + ks * 32);
#pragma unroll
                for (int tp = 0; tp < 2; tp++) {
                    unsigned bh[4];
                    ldsm_x4(bh, bAddr + tp * 1280 + ks * 32);
#pragma unroll
                    for (int mt = 0; mt < 2; mt++) {
                        mma_f16(acc[mt][2 * tp],     ah[mt], bh);
                        mma_f16(acc[mt][2 * tp + 1], ah[mt], bh + 2);
                    }
                }
            }
            cur = (cur == 2) ? 0 : cur + 1;
            nxt = (nxt == 2) ? 0 : nxt + 1;
        }
        __syncthreads();

#pragma unroll
        for (int mt = 0; mt < 2; mt++) {
            int gr = row0 + warp_m + mt * 16 + (lane >> 2);
#pragma unroll
            for (int nf = 0; nf < 4; nf++) {
                int gc = col0 + warp_n + nf * 8 + (lane & 3) * 2;
                float b0 = bias[gc], b1 = bias[gc + 1];
                float2 v0, v1;
                v0.x = fmaxf(fmaf(acc[mt][nf][0], osc, b0), 0.f);
                v0.y = fmaxf(fmaf(acc[mt][nf][1], osc, b1), 0.f);
                v1.x = fmaxf(fmaf(acc[mt][nf][2], osc, b0), 0.f);
                v1.y = fmaxf(fmaf(acc[mt][nf][3], osc, b1), 0.f);
                *reinterpret_cast<float2*>(&C[(size_t)gr * 1024 + gc]) = v0;
                *reinterpret_cast<float2*>(&C[(size_t)(gr + 8) * 1024 + gc]) = v1;
            }
        }
    }
}

// ---- LayerNorm (shuffle reduce); SPLIT: 0 none, 1 hi, 2 both; ZN: znorm --
template<int SPLIT, bool ZN>
__global__ __launch_bounds__(256)
void layernorm_k(const float* __restrict__ X, const float* __restrict__ g,
                 const float* __restrict__ b, float* __restrict__ Y)
{
    __shared__ float wpart[8];
    __shared__ double zpart[8];
    const int row = blockIdx.x;
    const int tid = threadIdx.x;
    const int lane = tid & 31, wid = tid >> 5;
    const float* x = X + (size_t)row * DM;
    float4 v = *reinterpret_cast<const float4*>(&x[tid * 4]);

    float s = v.x + v.y + v.z + v.w;
#pragma unroll
    for (int o = 16; o > 0; o >>= 1) s += __shfl_xor_sync(0xffffffffu, s, o);
    if (lane == 0) wpart[wid] = s;
    __syncthreads();
    float m = (wpart[0] + wpart[1] + wpart[2] + wpart[3]
             + wpart[4] + wpart[5] + wpart[6] + wpart[7]) * (1.f / 1024.f);
    __syncthreads();

    float dx = __fsub_rn(v.x, m), dy = __fsub_rn(v.y, m);
    float dz = __fsub_rn(v.z, m), dw = __fsub_rn(v.w, m);
    float s2 = dx * dx + dy * dy + dz * dz + dw * dw;
#pragma unroll
    for (int o = 16; o > 0; o >>= 1) s2 += __shfl_xor_sync(0xffffffffu, s2, o);
    if (lane == 0) wpart[wid] = s2;
    __syncthreads();
    float var = (wpart[0] + wpart[1] + wpart[2] + wpart[3]
               + wpart[4] + wpart[5] + wpart[6] + wpart[7]) * (1.f / 1024.f);
    float sc = rsqrt_approx(__fadd_rn(var, 1e-5f));

    float4 gg = *reinterpret_cast<const float4*>(&g[tid * 4]);
    float4 bb = *reinterpret_cast<const float4*>(&b[tid * 4]);
    float4 o4;
    o4.x = __fadd_rn(__fmul_rn(__fmul_rn(dx, sc), gg.x), bb.x);
    o4.y = __fadd_rn(__fmul_rn(__fmul_rn(dy, sc), gg.y), bb.y);
    o4.z = __fadd_rn(__fmul_rn(__fmul_rn(dz, sc), gg.z), bb.z);
    o4.w = __fadd_rn(__fmul_rn(__fmul_rn(dw, sc), gg.w), bb.w);
    *reinterpret_cast<float4*>(&Y[(size_t)row * DM + tid * 4]) = o4;

    if (SPLIT >= 1) {
        unsigned* au = reinterpret_cast<unsigned*>(g_asp);
        size_t bu = (size_t)row * 512 + tid * 2;
        __half2 h0 = __floats2half2_rn(o4.x, o4.y);
        __half2 h1 = __floats2half2_rn(o4.z, o4.w);
        au[bu]     = *reinterpret_cast<unsigned*>(&h0);
        au[bu + 1] = *reinterpret_cast<unsigned*>(&h1);
        if (SPLIT == 2) {
            float2 f0 = __half22float2(h0), f1 = __half22float2(h1);
            __half2 l0 = __floats2half2_rn((o4.x - f0.x) * LO_SCALE, (o4.y - f0.y) * LO_SCALE);
            __half2 l1 = __floats2half2_rn((o4.z - f1.x) * LO_SCALE, (o4.w - f1.y) * LO_SCALE);
            au[4194304 + bu]     = *reinterpret_cast<unsigned*>(&l0);
            au[4194304 + bu + 1] = *reinterpret_cast<unsigned*>(&l1);
        }
    }
    if (ZN) {
        double zs = (double)o4.x * o4.x + (double)o4.y * o4.y
                  + (double)o4.z * o4.z + (double)o4.w * o4.w;
#pragma unroll
        for (int o = 16; o > 0; o >>= 1) zs += __shfl_xor_sync(0xffffffffu, zs, o);
        if (lane == 0) zpart[wid] = zs;
        __syncthreads();
        if (tid < 4)
            g_znorm[row * 4 + tid] = (float)(zpart[2 * tid] + zpart[2 * tid + 1]);
    }
}

// ------- VQ: fp8 mma.sync sweep (3-stage pipeline) + exact refinement -----
#define STR8 272
#define VQ8_BUF (64*STR8)
#define VQ8_SMEM (3*VQ8_BUF)

__device__ __forceinline__ void insert4(float* L, int* C, float d, int code)
{
    if (d < L[3]) {
        float dd = d; int cc = code;
#pragma unroll
        for (int s = 0; s < 4; s++) {
            if (dd < L[s]) {
                float tf = L[s]; int ti = C[s];
                L[s] = dd; C[s] = cc; dd = tf; cc = ti;
            }
        }
    }
}

#define VQ8_PREFETCH(n0, buf)                                                 \
    do {                                                                      \
        const char* srcc = reinterpret_cast<const char*>(g_cb8) + (size_t)(n0) * 256; \
        uint32_t dstb = smBase + (buf) * VQ8_BUF;                             \
        _Pragma("unroll")                                                     \
        for (int j = 0; j < 4; j++) {                                         \
            int idx = tid + j * 256;                                          \
            int code = idx >> 4, q = idx & 15;                                \
            cp16(dstb + code * STR8 + q * 16, srcc + (size_t)idx * 16);       \
        }                                                                     \
    } while (0)

__global__ __launch_bounds__(256, 2)
void vq_mma_k(const float* __restrict__ Z, const float* __restrict__ CB,
              int* __restrict__ out_idx)
{
    extern __shared__ char sm[];
    const int tid  = threadIdx.x;
    const int lane = tid & 31;
    const int wid  = tid >> 5;
    const int row0 = blockIdx.x * 128;
    const uint32_t smBase = smem_u32(sm);

    // ---- stage z as e4m3 (x16) into buffer 0 region, hoist A frags ----
#pragma unroll
    for (int j = 0; j < 32; j++) {
        int idx = tid + j * 256;
        int m = idx >> 6, b4 = (idx & 63) * 4;
        float4 v = *reinterpret_cast<const float4*>(Z + (size_t)(row0 + m) * ED + b4);
        unsigned short l = f2e4m3x2(v.x * Z8SCALE, v.y * Z8SCALE);
        unsigned short h = f2e4m3x2(v.z * Z8SCALE, v.w * Z8SCALE);
        *reinterpret_cast<unsigned*>(sm + m * STR8 + b4) = (unsigned)l | ((unsigned)h << 16);
    }
    __syncthreads();

    unsigned a[8][4];
    {
        int rowA = wid * 16 + (lane & 15);
        int kofs = (lane & 16) ? 16 : 0;
        uint32_t base = smBase + rowA * STR8 + kofs;
#pragma unroll
        for (int ks = 0; ks < 8; ks++)
            ldsm_x4(a[ks], base + ks * 32);
    }
    __syncthreads();

    float L0[4], L1[4]; int C0[4], C1[4];
#pragma unroll
    for (int e = 0; e < 4; e++) { L0[e] = L1[e] = 3.4e38f; C0[e] = C1[e] = 0x7fffffff; }

    const uint32_t bOff = (uint32_t)((lane & 7) + ((lane & 16) ? 8 : 0)) * STR8
                        + ((lane & 8) ? 16 : 0);
    const int r  = lane >> 2;
    const int c2 = (lane & 3) * 2;

    VQ8_PREFETCH(0, 0);
    CP_COMMIT();
    VQ8_PREFETCH(64, 1);
    CP_COMMIT();

    int cur = 0, nxt = 2;
    for (int ci = 0; ci < 128; ci++) {
        const int n0 = ci * 64;
        if (ci < 127) CP_WAIT1(); else CP_WAIT0();
        __syncthreads();
        if (ci + 2 < 128) {
            VQ8_PREFETCH(n0 + 128, nxt);
            CP_COMMIT();
        }

        const uint32_t bB = smBase + cur * VQ8_BUF + bOff;

        float acc[8][4];
#pragma unroll
        for (int t = 0; t < 8; t++) { acc[t][0] = acc[t][1] = acc[t][2] = acc[t][3] = 0.f; }

#pragma unroll
        for (int ks = 0; ks < 8; ks++) {
#pragma unroll
            for (int tp = 0; tp < 4; tp++) {
                unsigned bb[4];
                ldsm_x4(bb, bB + tp * 16 * STR8 + ks * 32);
                mma_e4m3(acc[2 * tp],     a[ks], bb);
                mma_e4m3(acc[2 * tp + 1], a[ks], bb + 2);
            }
        }

        const float2* cn2 = reinterpret_cast<const float2*>(g_cnorm + n0);
#pragma unroll
        for (int t = 0; t < 8; t++) {
            int cb = t * 8 + c2;
            float2 c01 = cn2[cb >> 1];
            insert4(L0, C0, fmaf(acc[t][0], D8SCALE, c01.x), n0 + cb);
            insert4(L0, C0, fmaf(acc[t][1], D8SCALE, c01.y), n0 + cb + 1);
            insert4(L1, C1, fmaf(acc[t][2], D8SCALE, c01.x), n0 + cb);
            insert4(L1, C1, fmaf(acc[t][3], D8SCALE, c01.y), n0 + cb + 1);
        }
        cur = (cur == 2) ? 0 : cur + 1;
        nxt = (nxt == 2) ? 0 : nxt + 1;
    }
    __syncthreads();

    float* dS = reinterpret_cast<float*>(sm);
    int*   cS = reinterpret_cast<int*>(sm + 8192);
    {
        int base0 = (wid * 16 + r)     * 16 + (lane & 3) * 4;
        int base1 = (wid * 16 + r + 8) * 16 + (lane & 3) * 4;
#pragma unroll
        for (int e = 0; e < 4; e++) {
            dS[base0 + e] = L0[e]; cS[base0 + e] = C0[e];
            dS[base1 + e] = L1[e]; cS[base1 + e] = C1[e];
        }
    }
    __syncthreads();

    if (tid < 128) {
        const int row = row0 + tid;
        const float* dr = dS + tid * 16;
        const int*   cr = cS + tid * 16;
        float amin = dr[0];
#pragma unroll
        for (int e = 1; e < 16; e++) amin = fminf(amin, dr[e]);
        const float thr = amin + VQ_MARGIN8;
        const float zn = g_znorm[row];
        const float4* z4 = reinterpret_cast<const float4*>(Z + (size_t)row * ED);
        float best = 3.4e38f; int bi = 0x7fffffff;
        for (int e = 0; e < 16; e++) {
            if (dr[e] <= thr) {
                int code = cr[e];
                const float4* c4 = reinterpret_cast<const float4*>(CB + (size_t)code * ED);
                float accv = 0.f;
#pragma unroll 8
                for (int i = 0; i < 64; i++) {
                    float4 zv = z4[i], cv = c4[i];
                    accv = fmaf(zv.x, cv.x, accv);
                    accv = fmaf(zv.y, cv.y, accv);
                    accv = fmaf(zv.z, cv.z, accv);
                    accv = fmaf(zv.w, cv.w, accv);
                }
                float dex = __fsub_rn(__fadd_rn(zn, g_cnorm[code]), __fmul_rn(2.f, accv));
                if (dex < best || (dex == best && code < bi)) { best = dex; bi = code; }
            }
        }
        out_idx[row] = bi;
    }
}

// ---------------- histogram zero ------------------------------------------
__global__ __launch_bounds__(256)
void zero_hist_k()
{
    int i = blockIdx.x * 256 + threadIdx.x;
    if (i < KC) g_hist[i] = 0;
}

// ---- gather: ST rounding -> fp16 hi plane (x128) + hist + loss partial ---
__global__ __launch_bounds__(256)
void gather_hist_k(const float* __restrict__ CB)
{
    __shared__ double red[256];
    int warp = (blockIdx.x * 256 + threadIdx.x) >> 5;
    int lane = threadIdx.x & 31;
    int n = g_idx[warp];
    const float4* src = reinterpret_cast<const float4*>(CB + (size_t)n * ED);
    const float4* zsrc = reinterpret_cast<const float4*>(g_z + (size_t)warp * ED);
    unsigned* au = reinterpret_cast<unsigned*>(g_asp);
    double ls = 0.0;
#pragma unroll
    for (int h = 0; h < 2; h++) {
        float4 q = src[lane + h * 32];
        float4 z = zsrc[lane + h * 32];
        float dxx = __fsub_rn(q.x, z.x), dyy = __fsub_rn(q.y, z.y);
        float dzz = __fsub_rn(q.z, z.z), dww = __fsub_rn(q.w, z.w);
        float4 o;
        o.x = __fadd_rn(z.x, dxx);
        o.y = __fadd_rn(z.y, dyy);
        o.z = __fadd_rn(z.z, dzz);
        o.w = __fadd_rn(z.w, dww);
        float ex = __fsub_rn(o.x, z.x), ey = __fsub_rn(o.y, z.y);
        float ez = __fsub_rn(o.z, z.z), ew = __fsub_rn(o.w, z.w);
        ls += (double)ex * ex + (double)ey * ey + (double)ez * ez + (double)ew * ew;
        __half2 h0 = __floats2half2_rn(o.x * Q_SCALE, o.y * Q_SCALE);
        __half2 h1 = __floats2half2_rn(o.z * Q_SCALE, o.w * Q_SCALE);
        size_t bu = (size_t)warp * 128 + (size_t)(lane + h * 32) * 2;
        au[bu]     = *reinterpret_cast<unsigned*>(&h0);
        au[bu + 1] = *reinterpret_cast<unsigned*>(&h1);
    }
    if (lane == 0) atomicAdd(&g_hist[n], 1);
    red[threadIdx.x] = ls;
    __syncthreads();
    for (int o = 128; o > 0; o >>= 1) {
        if (threadIdx.x < o) red[threadIdx.x] += red[threadIdx.x + o];
        __syncthreads();
    }
    if (threadIdx.x == 0) g_part[blockIdx.x] = red[0];
}

// ---------------- finalize loss + perplexity ------------------------------
__global__ __launch_bounds__(256)
void finalize_k(float* __restrict__ out)
{
    __shared__ double red[256];
    int t = threadIdx.x;
    double s = 0.0;
    for (int k = 0; k < 16; k++) s += g_part[t + k * 256];
    red[t] = s;
    __syncthreads();
    for (int o = 128; o > 0; o >>= 1) { if (t < o) red[t] += red[t + o]; __syncthreads(); }
    double total = red[0];
    __syncthreads();
    double ps = 0.0;
    for (int k = 0; k < 32; k++) {
        int idx = t + k * 256;
        float p = (float)g_hist[idx] / 32768.f;
        ps += (double)__fmul_rn(p, logf(__fadd_rn(p, 1e-10f)));
    }
    red[t] = ps;
    __syncthreads();
    for (int o = 128; o > 0; o >>= 1) { if (t < o) red[t] += red[t + o]; __syncthreads(); }
    if (t == 0) {
        float m = (float)(total / 8388608.0);
        out[OUTN]     = __fadd_rn(m, __fmul_rn(0.25f, m));
        out[OUTN + 1] = expf(-(float)red[0]);
    }
}

// ---------------- launch ---------------------------------------------------
extern "C" void kernel_launch(void* const* d_in, const int* in_sizes, int n_in,
                              void* d_out, int out_size)
{
    const float* x    = (const float*)d_in[0];
    const float* We1  = (const float*)d_in[1];
    const float* be1  = (const float*)d_in[2];
    const float* ge1  = (const float*)d_in[3];
    const float* bne1 = (const float*)d_in[4];
    const float* We2  = (const float*)d_in[5];
    const float* be2  = (const float*)d_in[6];
    const float* ge2  = (const float*)d_in[7];
    const float* bne2 = (const float*)d_in[8];
    const float* Wd1  = (const float*)d_in[9];
    const float* bd1  = (const float*)d_in[10];
    const float* gd1  = (const float*)d_in[11];
    const float* bnd1 = (const float*)d_in[12];
    const float* Wd2  = (const float*)d_in[13];
    const float* bd2  = (const float*)d_in[14];
    const float* gd2  = (const float*)d_in[15];
    const float* bnd2 = (const float*)d_in[16];
    const float* CB   = (const float*)d_in[17];
    float* out = (float*)d_out;

    float *bufA, *bufB, *zp;
    int *idxp;
    __half *wt, *asp;
    cudaGetSymbolAddress((void**)&bufA, g_bufA);
    cudaGetSymbolAddress((void**)&bufB, g_bufB);
    cudaGetSymbolAddress((void**)&zp,   g_z);
    cudaGetSymbolAddress((void**)&idxp, g_idx);
    cudaGetSymbolAddress((void**)&wt,   g_wt);
    cudaGetSymbolAddress((void**)&asp,  g_asp);

    int nsm = 148;
    cudaDeviceGetAttribute(&nsm, cudaDevAttrMultiProcessorCount, 0);
    const int pgrid = 2 * nsm;

    cudaFuncSetAttribute(vq_mma_k, cudaFuncAttributeMaxDynamicSharedMemorySize, VQ8_SMEM);
    cudaFuncSetAttribute(gemm_mma_k, cudaFuncAttributeMaxDynamicSharedMemorySize, 3 * GBUF);
    cudaFuncSetAttribute(gemm1_mma_k, cudaFuncAttributeMaxDynamicSharedMemorySize, 3 * G1BUF);

    dim3 wg(32, 32, 4);

    // prep
    wsplit_k<<<wg, 256>>>(We1, We2, Wd1, Wd2);
    asplit_k<<<16384, 256>>>(x);
    cbprep_k<<<KC / 8, 256>>>(CB);
    zero_hist_k<<<KC / 256, 256>>>();

    // encoder (persistent split-2 fp16 GEMMs; LN1 emits planes, LN2 emits znorm)
    gemm_mma_k<<<pgrid, 256, 3 * GBUF>>>(asp, wt, be1, bufA);
    layernorm_k<2, false><<<TOK, 256>>>(bufA, ge1, bne1, bufB);
    gemm_mma_k<<<pgrid, 256, 3 * GBUF>>>(asp, wt + 1 * 2097152, be2, bufA);
    layernorm_k<0, true><<<TOK, 256>>>(bufA, ge2, bne2, zp);

    // vector quantization (fp8 sweep + exact refinement)
    vq_mma_k<<<NFLAT / 128, 256, VQ8_SMEM>>>(zp, CB, idxp);
    gather_hist_k<<<NFLAT / 8, 256>>>(CB);   // emits decoder planes + loss partials

    // decoder (persistent single-plane fp16 GEMMs)
    gemm1_mma_k<<<pgrid, 256, 3 * G1BUF>>>(asp, wt + 2 * 2097152, bd1, Q_INV, bufA);
    layernorm_k<1, false><<<TOK, 256>>>(bufA, gd1, bnd1, bufB);
    gemm1_mma_k<<<pgrid, 256, 3 * G1BUF>>>(asp, wt + 3 * 2097152, bd2, 1.0f, bufA);
    layernorm_k<0, false><<<TOK, 256>>>(bufA, gd2, bnd2, out);

    // scalars
    finalize_k<<<1, 256>>>(out);
}